// round 14
// baseline (speedup 1.0000x reference)
#include <cuda_runtime.h>
#include <cuda_fp16.h>
#include <cstdint>

// Problem dims (fixed by the reference)
#define NE 8
#define NT 1024
#define ND 2048
#define NI 4096

// ---------------------------------------------------------------------------
// __device__ scratch (alloc-free rule): fp16 copies of inputs + intermediate H
// g_gwh/g_iwh second halves and g_owh are filled by the GEMM1 half-launches'
// epilogues (distributed, non-redundant chunks).
// ---------------------------------------------------------------------------
__device__ __half g_xh [(size_t)NE * NT * ND];   //  32 MB
__device__ __half g_gwh[(size_t)NE * ND * NI];   // 134 MB
__device__ __half g_iwh[(size_t)NE * ND * NI];   // 134 MB
__device__ __half g_owh[(size_t)NE * NI * ND];   // 134 MB
__device__ __half g_H  [(size_t)NE * NT * NI];   //  67 MB

// ---------------------------------------------------------------------------
// PTX helpers (baseline sm_80+ instructions only — compute_103-safe)
// ---------------------------------------------------------------------------
__device__ __forceinline__ uint32_t smem_u32(const void* p) {
    uint32_t a;
    asm("{ .reg .u64 t; cvta.to.shared.u64 t, %1; cvt.u32.u64 %0, t; }"
        : "=r"(a) : "l"(p));
    return a;
}
__device__ __forceinline__ void cp16(uint32_t saddr, const void* g) {
    asm volatile("cp.async.cg.shared.global [%0], [%1], 16;"
                 :: "r"(saddr), "l"(g) : "memory");
}
__device__ __forceinline__ void cp_commit() {
    asm volatile("cp.async.commit_group;" ::: "memory");
}
template <int N> __device__ __forceinline__ void cp_wait() {
    asm volatile("cp.async.wait_group %0;" :: "n"(N) : "memory");
}
__device__ __forceinline__ void ldsm4(uint32_t* r, uint32_t a) {
    asm volatile("ldmatrix.sync.aligned.m8n8.x4.shared.b16 {%0,%1,%2,%3}, [%4];"
                 : "=r"(r[0]), "=r"(r[1]), "=r"(r[2]), "=r"(r[3]) : "r"(a));
}
__device__ __forceinline__ void ldsm4t(uint32_t* r, uint32_t a) {
    asm volatile("ldmatrix.sync.aligned.m8n8.x4.trans.shared.b16 {%0,%1,%2,%3}, [%4];"
                 : "=r"(r[0]), "=r"(r[1]), "=r"(r[2]), "=r"(r[3]) : "r"(a));
}
__device__ __forceinline__ void mma16816(float* c, const uint32_t* a,
                                         uint32_t b0, uint32_t b1) {
    asm volatile(
        "mma.sync.aligned.m16n8k16.row.col.f32.f16.f16.f32 "
        "{%0,%1,%2,%3}, {%4,%5,%6,%7}, {%8,%9}, {%0,%1,%2,%3};"
        : "+f"(c[0]), "+f"(c[1]), "+f"(c[2]), "+f"(c[3])
        : "r"(a[0]), "r"(a[1]), "r"(a[2]), "r"(a[3]), "r"(b0), "r"(b1));
}
__device__ __forceinline__ uint32_t h2u(float lo, float hi) {
    __half2 h = __floats2half2_rn(lo, hi);
    return *(uint32_t*)&h;
}
#define SWZ(b) ((b) ^ (((b) >> 3) & 0x70))   // SW128: conflict-free ldmatrix

// ---------------------------------------------------------------------------
// Kernel 0a: fp32 -> fp16 conversion for x (grid-stride; streaming)
// ---------------------------------------------------------------------------
__global__ void cvt_f2h(const float* __restrict__ s, __half* __restrict__ d,
                        size_t n)
{
    size_t i = ((size_t)blockIdx.x * blockDim.x + threadIdx.x) * 8;
    size_t stride = (size_t)gridDim.x * blockDim.x * 8;
    for (; i < n; i += stride) {
        float4 v0 = __ldcs((const float4*)(s + i));
        float4 v1 = __ldcs((const float4*)(s + i + 4));
        uint4 o;
        o.x = h2u(v0.x, v0.y); o.y = h2u(v0.z, v0.w);
        o.z = h2u(v1.x, v1.y); o.w = h2u(v1.z, v1.w);
        __stcs((uint4*)(d + i), o);
    }
}

// ---------------------------------------------------------------------------
// Kernel 0b: convert columns [0, NI/2) of gw and iw (first-half slabs only).
// 32768 logical rows (gw rows then iw rows) of 2048 contiguous floats.
// ---------------------------------------------------------------------------
__global__ void cvt_w_half1(const float* __restrict__ gw,
                            const float* __restrict__ iw)
{
    for (size_t g = blockIdx.x; g < 2u * NE * ND; g += gridDim.x) {
        const float* src = ((g < (size_t)NE * ND) ? gw : iw)
                           + (g & ((size_t)NE * ND - 1)) * NI;
        __half* dst = ((g < (size_t)NE * ND) ? g_gwh : g_iwh)
                      + (g & ((size_t)NE * ND - 1)) * NI;
        for (int j = threadIdx.x; j < (NI / 2) / 4; j += blockDim.x) {
            float4 v = __ldcs((const float4*)src + j);
            __stcs((uint2*)dst + j, make_uint2(h2u(v.x, v.y), h2u(v.z, v.w)));
        }
    }
}

// ===========================================================================
// Kernel 1: fused dual GEMM + GLU (R10 mainloop: two barriers, loads after
//   MMA block). Launched twice (half=0: n in [0,2048); half=1: [2048,4096)).
//   EPILOGUE carries the distributed converts (overlapped with other CTAs'
//   mainloops; never delays this CTA's tensor work):
//     half=0 -> converts gw/iw columns [2048,4096)   (needed by half=1)
//     half=1 -> converts ow (all)                    (needed by GEMM2)
//   BM=128, BN=64, BK=64, 3-stage cp.async, 8 warps; smem 96KB; 2 CTAs/SM.
// ===========================================================================
__global__ __launch_bounds__(256, 2)
void glu_mma_kernel(const float* __restrict__ gw, const float* __restrict__ iw,
                    const float* __restrict__ ow, int half)
{
    extern __shared__ char smem[];
    const uint32_t sb = smem_u32(smem);
    const int tid = threadIdx.x, warp = tid >> 5, lane = tid & 31;
    const int wm = warp & 3, wn = warp >> 2;
    const int m0 = blockIdx.x * 128, e = blockIdx.z;
    const int n0 = half * (NI / 2) + blockIdx.y * 64;

    const __half* Ab = g_xh  + ((size_t)e * NT + m0) * ND;
    const __half* Gb = g_gwh + ((size_t)e * ND) * NI + n0;
    const __half* Ub = g_iwh + ((size_t)e * ND) * NI + n0;

    // per-thread ldmatrix byte offsets (pre-swizzle)
    int aoff[2], boff[2];
    #pragma unroll
    for (int i = 0; i < 2; i++)
        aoff[i] = (wm * 32 + i * 16 + (lane & 15)) * 128 + (lane >> 4) * 16;
    #pragma unroll
    for (int j = 0; j < 2; j++)
        boff[j] = (lane & 15) * 128 + (wn * 32 + j * 16 + (lane >> 4) * 8) * 2;

    float accG[2][4][4] = {}, accU[2][4][4] = {};

    auto load_stage = [&](int kt, int s) {
        const uint32_t sbase = sb + s * 32768;
        const int k0 = kt * 64;
        #pragma unroll
        for (int i = 0; i < 4; i++) {            // A: 128x64 halves
            int f = tid + i * 256, r = f >> 3, c = (f & 7) * 8;
            cp16(sbase + SWZ(r * 128 + c * 2), Ab + (size_t)r * ND + k0 + c);
        }
        #pragma unroll
        for (int i = 0; i < 2; i++) {            // Bg/Bu: 64x64 halves each
            int f = tid + i * 256, r = f >> 3, c = (f & 7) * 8;
            size_t go = (size_t)(k0 + r) * NI + c;
            cp16(sbase + 16384 + SWZ(r * 128 + c * 2), Gb + go);
            cp16(sbase + 24576 + SWZ(r * 128 + c * 2), Ub + go);
        }
    };

    constexpr int KT = ND / 64;   // 32
    load_stage(0, 0); cp_commit();
    load_stage(1, 1); cp_commit();

    for (int kt = 0; kt < KT; ++kt) {
        cp_wait<1>();
        __syncthreads();
        const int s = kt % 3;
        const uint32_t sA = sb + s * 32768, sBg = sA + 16384, sBu = sA + 24576;
        #pragma unroll
        for (int kk = 0; kk < 4; ++kk) {
            uint32_t a[2][4], bg[2][4], bu[2][4];
            #pragma unroll
            for (int i = 0; i < 2; i++) ldsm4(a[i], sA + SWZ(aoff[i] + kk * 32));
            #pragma unroll
            for (int j = 0; j < 2; j++) {
                ldsm4t(bg[j], sBg + SWZ(boff[j] + kk * 2048));
                ldsm4t(bu[j], sBu + SWZ(boff[j] + kk * 2048));
            }
            #pragma unroll
            for (int i = 0; i < 2; i++)
                #pragma unroll
                for (int j = 0; j < 4; j++) {
                    mma16816(accG[i][j], a[i], bg[j >> 1][(j & 1) * 2],
                             bg[j >> 1][(j & 1) * 2 + 1]);
                    mma16816(accU[i][j], a[i], bu[j >> 1][(j & 1) * 2],
                             bu[j >> 1][(j & 1) * 2 + 1]);
                }
        }
        __syncthreads();
        if (kt + 2 < KT) load_stage(kt + 2, (kt + 2) % 3);
        cp_commit();
    }

    // Epilogue part 1: H = silu(G)*U, fp16 store.
    __half* Hd = g_H + (size_t)e * NT * NI;
    const int rb = m0 + wm * 32 + (lane >> 2);
    const int cb = n0 + wn * 32 + (lane & 3) * 2;
    #pragma unroll
    for (int i = 0; i < 2; i++)
        #pragma unroll
        for (int j = 0; j < 4; j++)
            #pragma unroll
            for (int h = 0; h < 2; h++) {   // h=0: row, h=1: row+8
                float g0 = accG[i][j][h * 2],     u0 = accU[i][j][h * 2];
                float g1 = accG[i][j][h * 2 + 1], u1 = accU[i][j][h * 2 + 1];
                float h0 = (g0 / (1.0f + __expf(-g0))) * u0;
                float h1 = (g1 / (1.0f + __expf(-g1))) * u1;
                size_t off = (size_t)(rb + i * 16 + h * 8) * NI + cb + j * 8;
                *(__half2*)(Hd + off) = __floats2half2_rn(h0, h1);
            }

    // Epilogue part 2: distributed convert chunk (non-redundant; overlapped
    // with other CTAs' mainloops; consumed only by a LATER kernel launch).
    const size_t bid = (size_t)blockIdx.x +
                       (size_t)gridDim.x * (blockIdx.y +
                       (size_t)gridDim.y * blockIdx.z);     // 0..2047
    if (half == 0) {
        // gw/iw columns [NI/2, NI): 32768 logical rows of 2048 floats,
        // 16 rows per block.
        #pragma unroll
        for (int i = 0; i < 16; i++) {
            size_t g = bid * 16 + i;
            const float* src = ((g < (size_t)NE * ND) ? gw : iw)
                               + (g & ((size_t)NE * ND - 1)) * NI + NI / 2;
            __half* dst = ((g < (size_t)NE * ND) ? g_gwh : g_iwh)
                          + (g & ((size_t)NE * ND - 1)) * NI + NI / 2;
            #pragma unroll
            for (int j = 0; j < 2; j++) {
                int idx = (tid + j * 256) * 4;
                float4 v = __ldcs((const float4*)(src + idx));
                __stcs((uint2*)(dst + idx),
                       make_uint2(h2u(v.x, v.y), h2u(v.z, v.w)));
            }
        }
    } else {
        // ow full tensor: 67.1M elements / 2048 blocks = 32768 per block.
        const float* src = ow + bid * 32768;
        __half* dst = g_owh + bid * 32768;
        #pragma unroll
        for (int i = 0; i < 32; i++) {
            int idx = (tid + i * 256) * 4;
            float4 v = __ldcs((const float4*)(src + idx));
            __stcs((uint2*)(dst + idx),
                   make_uint2(h2u(v.x, v.y), h2u(v.z, v.w)));
        }
    }
}

// ===========================================================================
// Kernel 2: out = H @ op.  (R10 structure.)  BM=128, BN=128, BK=64, 3 stages,
//   8 warps (4x2).  smem = 96KB; 2 CTAs/SM via __launch_bounds__(256,2).
// ===========================================================================
__global__ __launch_bounds__(256, 2)
void out_mma_kernel(float* __restrict__ out)
{
    extern __shared__ char smem[];
    const uint32_t sb = smem_u32(smem);
    const int tid = threadIdx.x, warp = tid >> 5, lane = tid & 31;
    const int wm = warp & 3, wn = warp >> 2;
    const int m0 = blockIdx.x * 128, n0 = blockIdx.y * 128, e = blockIdx.z;

    const __half* Ab = g_H   + ((size_t)e * NT + m0) * NI;
    const __half* Bb = g_owh + ((size_t)e * NI) * ND + n0;

    int aoff[2];
    #pragma unroll
    for (int i = 0; i < 2; i++)
        aoff[i] = (wm * 32 + i * 16 + (lane & 15)) * 128 + (lane >> 4) * 16;
    // B: [64 k][128 n] stored as two [64][64] halves (128B rows each)
    int bhalf[4], boff[4];
    #pragma unroll
    for (int j = 0; j < 4; j++) {
        int c = wn * 64 + j * 16 + (lane >> 4) * 8;
        bhalf[j] = (c >> 6) * 8192;
        boff[j]  = (lane & 15) * 128 + (c & 63) * 2;
    }

    float acc[2][8][4] = {};

    auto load_stage = [&](int kt, int s) {
        const uint32_t sbase = sb + s * 32768;
        const int k0 = kt * 64;
        #pragma unroll
        for (int i = 0; i < 4; i++) {            // A: 128x64
            int f = tid + i * 256, r = f >> 3, c = (f & 7) * 8;
            cp16(sbase + SWZ(r * 128 + c * 2), Ab + (size_t)r * NI + k0 + c);
        }
        #pragma unroll
        for (int i = 0; i < 4; i++) {            // B: 64x128
            int f = tid + i * 256, r = f >> 4, c = (f & 15) * 8;
            cp16(sbase + 16384 + (c >> 6) * 8192 + SWZ(r * 128 + (c & 63) * 2),
                 Bb + (size_t)(k0 + r) * ND + c);
        }
    };

    constexpr int KT = NI / 64;   // 64
    load_stage(0, 0); cp_commit();
    load_stage(1, 1); cp_commit();

    for (int kt = 0; kt < KT; ++kt) {
        cp_wait<1>();
        __syncthreads();
        const int s = kt % 3;
        const uint32_t sA = sb + s * 32768, sB = sA + 16384;
        #pragma unroll
        for (int kk = 0; kk < 4; ++kk) {
            uint32_t a[2][4], b[4][4];
            #pragma unroll
            for (int i = 0; i < 2; i++) ldsm4(a[i], sA + SWZ(aoff[i] + kk * 32));
            #pragma unroll
            for (int j = 0; j < 4; j++)
                ldsm4t(b[j], sB + bhalf[j] + SWZ(boff[j] + kk * 2048));
            #pragma unroll
            for (int i = 0; i < 2; i++)
                #pragma unroll
                for (int j = 0; j < 8; j++)
                    mma16816(acc[i][j], a[i], b[j >> 1][(j & 1) * 2],
                             b[j >> 1][(j & 1) * 2 + 1]);
        }
        __syncthreads();
        if (kt + 2 < KT) load_stage(kt + 2, (kt + 2) % 3);
        cp_commit();
    }

    // Epilogue: fp32 stores
    float* Od = out + (size_t)e * NT * ND;
    const int rb = m0 + wm * 32 + (lane >> 2);
    const int cb = n0 + wn * 64 + (lane & 3) * 2;
    #pragma unroll
    for (int i = 0; i < 2; i++)
        #pragma unroll
        for (int j = 0; j < 8; j++)
            #pragma unroll
            for (int h = 0; h < 2; h++) {
                size_t off = (size_t)(rb + i * 16 + h * 8) * ND + cb + j * 8;
                float2 v = make_float2(acc[i][j][h * 2], acc[i][j][h * 2 + 1]);
                *(float2*)(Od + off) = v;
            }
}

// ---------------------------------------------------------------------------
// Harness entry. Inputs: x, gate_proj, inner_proj, output_proj (all fp32).
// Cascade: cvt(x, w-half1) -> glu half1 (epilogue converts w-half2)
//          -> glu half2 (epilogue converts ow) -> GEMM2.
// All graph-capturable, no allocations.
// ---------------------------------------------------------------------------
extern "C" void kernel_launch(void* const* d_in, const int* in_sizes, int n_in,
                              void* d_out, int out_size)
{
    const float* x  = (const float*)d_in[0];
    const float* gw = (const float*)d_in[1];
    const float* iw = (const float*)d_in[2];
    const float* ow = (const float*)d_in[3];
    float* out = (float*)d_out;

    __half* xh;
    cudaGetSymbolAddress((void**)&xh, g_xh);

    cvt_f2h<<<2048, 256>>>(x, xh, (size_t)NE * NT * ND);
    cvt_w_half1<<<2048, 256>>>(gw, iw);

    cudaFuncSetAttribute(glu_mma_kernel,
                         cudaFuncAttributeMaxDynamicSharedMemorySize, 98304);
    cudaFuncSetAttribute(out_mma_kernel,
                         cudaFuncAttributeMaxDynamicSharedMemorySize, 98304);

    // grid.x = m-tiles (fastest) so concurrent CTAs share B slabs in L2
    glu_mma_kernel<<<dim3(NT / 128, NI / 128, NE), 256, 98304>>>(gw, iw, ow, 0);
    glu_mma_kernel<<<dim3(NT / 128, NI / 128, NE), 256, 98304>>>(gw, iw, ow, 1);
    out_mma_kernel<<<dim3(NT / 128, ND / 128, NE), 256, 98304>>>(out);
}

// round 15
// speedup vs baseline: 1.0448x; 1.0448x over previous
#include <cuda_runtime.h>
#include <cuda_fp16.h>
#include <cstdint>

// Problem dims (fixed by the reference)
#define NE 8
#define NT 1024
#define ND 2048
#define NI 4096

// ---------------------------------------------------------------------------
// __device__ scratch (alloc-free rule): fp16 copies of inputs + intermediate H
// g_owh is filled by GEMM1's distributed EPILOGUE chunks (non-redundant).
// ---------------------------------------------------------------------------
__device__ __half g_xh [(size_t)NE * NT * ND];   //  32 MB
__device__ __half g_gwh[(size_t)NE * ND * NI];   // 134 MB
__device__ __half g_iwh[(size_t)NE * ND * NI];   // 134 MB
__device__ __half g_owh[(size_t)NE * NI * ND];   // 134 MB
__device__ __half g_H  [(size_t)NE * NT * NI];   //  67 MB

// ---------------------------------------------------------------------------
// PTX helpers (baseline sm_80+ instructions only — compute_103-safe)
// ---------------------------------------------------------------------------
__device__ __forceinline__ uint32_t smem_u32(const void* p) {
    uint32_t a;
    asm("{ .reg .u64 t; cvta.to.shared.u64 t, %1; cvt.u32.u64 %0, t; }"
        : "=r"(a) : "l"(p));
    return a;
}
__device__ __forceinline__ void cp16(uint32_t saddr, const void* g) {
    asm volatile("cp.async.cg.shared.global [%0], [%1], 16;"
                 :: "r"(saddr), "l"(g) : "memory");
}
__device__ __forceinline__ void cp_commit() {
    asm volatile("cp.async.commit_group;" ::: "memory");
}
template <int N> __device__ __forceinline__ void cp_wait() {
    asm volatile("cp.async.wait_group %0;" :: "n"(N) : "memory");
}
__device__ __forceinline__ void ldsm4(uint32_t* r, uint32_t a) {
    asm volatile("ldmatrix.sync.aligned.m8n8.x4.shared.b16 {%0,%1,%2,%3}, [%4];"
                 : "=r"(r[0]), "=r"(r[1]), "=r"(r[2]), "=r"(r[3]) : "r"(a));
}
__device__ __forceinline__ void ldsm4t(uint32_t* r, uint32_t a) {
    asm volatile("ldmatrix.sync.aligned.m8n8.x4.trans.shared.b16 {%0,%1,%2,%3}, [%4];"
                 : "=r"(r[0]), "=r"(r[1]), "=r"(r[2]), "=r"(r[3]) : "r"(a));
}
__device__ __forceinline__ void mma16816(float* c, const uint32_t* a,
                                         uint32_t b0, uint32_t b1) {
    asm volatile(
        "mma.sync.aligned.m16n8k16.row.col.f32.f16.f16.f32 "
        "{%0,%1,%2,%3}, {%4,%5,%6,%7}, {%8,%9}, {%0,%1,%2,%3};"
        : "+f"(c[0]), "+f"(c[1]), "+f"(c[2]), "+f"(c[3])
        : "r"(a[0]), "r"(a[1]), "r"(a[2]), "r"(a[3]), "r"(b0), "r"(b1));
}
__device__ __forceinline__ uint32_t h2u(float lo, float hi) {
    __half2 h = __floats2half2_rn(lo, hi);
    return *(uint32_t*)&h;
}
#define SWZ(b) ((b) ^ (((b) >> 3) & 0x70))   // SW128: conflict-free ldmatrix

// ---------------------------------------------------------------------------
// Kernel 0: fp32 -> fp16 conversion (grid-stride; streaming ld/st to spare L2)
// ---------------------------------------------------------------------------
__global__ void cvt_f2h(const float* __restrict__ s, __half* __restrict__ d,
                        size_t n)
{
    size_t i = ((size_t)blockIdx.x * blockDim.x + threadIdx.x) * 8;
    size_t stride = (size_t)gridDim.x * blockDim.x * 8;
    for (; i < n; i += stride) {
        float4 v0 = __ldcs((const float4*)(s + i));
        float4 v1 = __ldcs((const float4*)(s + i + 4));
        uint4 o;
        o.x = h2u(v0.x, v0.y); o.y = h2u(v0.z, v0.w);
        o.z = h2u(v1.x, v1.y); o.w = h2u(v1.z, v1.w);
        __stcs((uint4*)(d + i), o);
    }
}

// ===========================================================================
// Kernel 1: fused dual GEMM + GLU (R10 mainloop: two barriers, loads after
//   MMA block) + distributed, NON-redundant ow conversion in the EPILOGUE
//   (after this CTA's tensor work; overlapped by co-resident CTAs' mainloops;
//   ow is consumed only by GEMM2, which launches after this kernel).
//   BM=128, BN=64, BK=64, 3-stage cp.async, 8 warps; smem 96KB; 2 CTAs/SM.
// ===========================================================================
__global__ __launch_bounds__(256, 2)
void glu_mma_kernel(const float* __restrict__ ow)
{
    extern __shared__ char smem[];
    const uint32_t sb = smem_u32(smem);
    const int tid = threadIdx.x, warp = tid >> 5, lane = tid & 31;
    const int wm = warp & 3, wn = warp >> 2;
    const int m0 = blockIdx.x * 128, n0 = blockIdx.y * 64, e = blockIdx.z;

    const __half* Ab = g_xh  + ((size_t)e * NT + m0) * ND;
    const __half* Gb = g_gwh + ((size_t)e * ND) * NI + n0;
    const __half* Ub = g_iwh + ((size_t)e * ND) * NI + n0;

    // per-thread ldmatrix byte offsets (pre-swizzle)
    int aoff[2], boff[2];
    #pragma unroll
    for (int i = 0; i < 2; i++)
        aoff[i] = (wm * 32 + i * 16 + (lane & 15)) * 128 + (lane >> 4) * 16;
    #pragma unroll
    for (int j = 0; j < 2; j++)
        boff[j] = (lane & 15) * 128 + (wn * 32 + j * 16 + (lane >> 4) * 8) * 2;

    float accG[2][4][4] = {}, accU[2][4][4] = {};

    auto load_stage = [&](int kt, int s) {
        const uint32_t sbase = sb + s * 32768;
        const int k0 = kt * 64;
        #pragma unroll
        for (int i = 0; i < 4; i++) {            // A: 128x64 halves
            int f = tid + i * 256, r = f >> 3, c = (f & 7) * 8;
            cp16(sbase + SWZ(r * 128 + c * 2), Ab + (size_t)r * ND + k0 + c);
        }
        #pragma unroll
        for (int i = 0; i < 2; i++) {            // Bg/Bu: 64x64 halves each
            int f = tid + i * 256, r = f >> 3, c = (f & 7) * 8;
            size_t go = (size_t)(k0 + r) * NI + c;
            cp16(sbase + 16384 + SWZ(r * 128 + c * 2), Gb + go);
            cp16(sbase + 24576 + SWZ(r * 128 + c * 2), Ub + go);
        }
    };

    constexpr int KT = ND / 64;   // 32
    load_stage(0, 0); cp_commit();
    load_stage(1, 1); cp_commit();

    for (int kt = 0; kt < KT; ++kt) {
        cp_wait<1>();
        __syncthreads();
        const int s = kt % 3;
        const uint32_t sA = sb + s * 32768, sBg = sA + 16384, sBu = sA + 24576;
        #pragma unroll
        for (int kk = 0; kk < 4; ++kk) {
            uint32_t a[2][4], bg[2][4], bu[2][4];
            #pragma unroll
            for (int i = 0; i < 2; i++) ldsm4(a[i], sA + SWZ(aoff[i] + kk * 32));
            #pragma unroll
            for (int j = 0; j < 2; j++) {
                ldsm4t(bg[j], sBg + SWZ(boff[j] + kk * 2048));
                ldsm4t(bu[j], sBu + SWZ(boff[j] + kk * 2048));
            }
            #pragma unroll
            for (int i = 0; i < 2; i++)
                #pragma unroll
                for (int j = 0; j < 4; j++) {
                    mma16816(accG[i][j], a[i], bg[j >> 1][(j & 1) * 2],
                             bg[j >> 1][(j & 1) * 2 + 1]);
                    mma16816(accU[i][j], a[i], bu[j >> 1][(j & 1) * 2],
                             bu[j >> 1][(j & 1) * 2 + 1]);
                }
        }
        __syncthreads();
        if (kt + 2 < KT) load_stage(kt + 2, (kt + 2) % 3);
        cp_commit();
    }

    // Epilogue part 1: H = silu(G)*U, fp16 store.
    __half* Hd = g_H + (size_t)e * NT * NI;
    const int rb = m0 + wm * 32 + (lane >> 2);
    const int cb = n0 + wn * 32 + (lane & 3) * 2;
    #pragma unroll
    for (int i = 0; i < 2; i++)
        #pragma unroll
        for (int j = 0; j < 4; j++)
            #pragma unroll
            for (int h = 0; h < 2; h++) {   // h=0: row, h=1: row+8
                float g0 = accG[i][j][h * 2],     u0 = accU[i][j][h * 2];
                float g1 = accG[i][j][h * 2 + 1], u1 = accU[i][j][h * 2 + 1];
                float h0 = (g0 / (1.0f + __expf(-g0))) * u0;
                float h1 = (g1 / (1.0f + __expf(-g1))) * u1;
                size_t off = (size_t)(rb + i * 16 + h * 8) * NI + cb + j * 8;
                *(__half2*)(Hd + off) = __floats2half2_rn(h0, h1);
            }

    // Epilogue part 2: distributed ow convert — distinct 16384-element chunk
    // per CTA (64KB read / 32KB write), after all tensor work.
    {
        const size_t bid = (size_t)blockIdx.x +
                           (size_t)gridDim.x * (blockIdx.y +
                           (size_t)gridDim.y * blockIdx.z);     // 0..4095
        const float* src = ow + bid * 16384;
        __half* dst = g_owh + bid * 16384;
        #pragma unroll
        for (int i = 0; i < 16; i++) {
            int f = (tid + i * 256) * 4;
            float4 v = __ldcs((const float4*)(src + f));
            __stcs((uint2*)(dst + f), make_uint2(h2u(v.x, v.y), h2u(v.z, v.w)));
        }
    }
}

// ===========================================================================
// Kernel 2: out = H @ op.  (R10 structure.)  BM=128, BN=128, BK=64, 3 stages,
//   8 warps (4x2).  smem = 96KB; 2 CTAs/SM via __launch_bounds__(256,2).
// ===========================================================================
__global__ __launch_bounds__(256, 2)
void out_mma_kernel(float* __restrict__ out)
{
    extern __shared__ char smem[];
    const uint32_t sb = smem_u32(smem);
    const int tid = threadIdx.x, warp = tid >> 5, lane = tid & 31;
    const int wm = warp & 3, wn = warp >> 2;
    const int m0 = blockIdx.x * 128, n0 = blockIdx.y * 128, e = blockIdx.z;

    const __half* Ab = g_H   + ((size_t)e * NT + m0) * NI;
    const __half* Bb = g_owh + ((size_t)e * NI) * ND + n0;

    int aoff[2];
    #pragma unroll
    for (int i = 0; i < 2; i++)
        aoff[i] = (wm * 32 + i * 16 + (lane & 15)) * 128 + (lane >> 4) * 16;
    // B: [64 k][128 n] stored as two [64][64] halves (128B rows each)
    int bhalf[4], boff[4];
    #pragma unroll
    for (int j = 0; j < 4; j++) {
        int c = wn * 64 + j * 16 + (lane >> 4) * 8;
        bhalf[j] = (c >> 6) * 8192;
        boff[j]  = (lane & 15) * 128 + (c & 63) * 2;
    }

    float acc[2][8][4] = {};

    auto load_stage = [&](int kt, int s) {
        const uint32_t sbase = sb + s * 32768;
        const int k0 = kt * 64;
        #pragma unroll
        for (int i = 0; i < 4; i++) {            // A: 128x64
            int f = tid + i * 256, r = f >> 3, c = (f & 7) * 8;
            cp16(sbase + SWZ(r * 128 + c * 2), Ab + (size_t)r * NI + k0 + c);
        }
        #pragma unroll
        for (int i = 0; i < 4; i++) {            // B: 64x128
            int f = tid + i * 256, r = f >> 4, c = (f & 15) * 8;
            cp16(sbase + 16384 + (c >> 6) * 8192 + SWZ(r * 128 + (c & 63) * 2),
                 Bb + (size_t)(k0 + r) * ND + c);
        }
    };

    constexpr int KT = NI / 64;   // 64
    load_stage(0, 0); cp_commit();
    load_stage(1, 1); cp_commit();

    for (int kt = 0; kt < KT; ++kt) {
        cp_wait<1>();
        __syncthreads();
        const int s = kt % 3;
        const uint32_t sA = sb + s * 32768, sB = sA + 16384;
        #pragma unroll
        for (int kk = 0; kk < 4; ++kk) {
            uint32_t a[2][4], b[4][4];
            #pragma unroll
            for (int i = 0; i < 2; i++) ldsm4(a[i], sA + SWZ(aoff[i] + kk * 32));
            #pragma unroll
            for (int j = 0; j < 4; j++)
                ldsm4t(b[j], sB + bhalf[j] + SWZ(boff[j] + kk * 2048));
            #pragma unroll
            for (int i = 0; i < 2; i++)
                #pragma unroll
                for (int j = 0; j < 8; j++)
                    mma16816(acc[i][j], a[i], b[j >> 1][(j & 1) * 2],
                             b[j >> 1][(j & 1) * 2 + 1]);
        }
        __syncthreads();
        if (kt + 2 < KT) load_stage(kt + 2, (kt + 2) % 3);
        cp_commit();
    }

    // Epilogue: fp32 stores
    float* Od = out + (size_t)e * NT * ND;
    const int rb = m0 + wm * 32 + (lane >> 2);
    const int cb = n0 + wn * 64 + (lane & 3) * 2;
    #pragma unroll
    for (int i = 0; i < 2; i++)
        #pragma unroll
        for (int j = 0; j < 8; j++)
            #pragma unroll
            for (int h = 0; h < 2; h++) {
                size_t off = (size_t)(rb + i * 16 + h * 8) * ND + cb + j * 8;
                float2 v = make_float2(acc[i][j][h * 2], acc[i][j][h * 2 + 1]);
                *(float2*)(Od + off) = v;
            }
}

// ---------------------------------------------------------------------------
// Harness entry. Inputs: x, gate_proj, inner_proj, output_proj (all fp32).
// Sequence: cvt x/gw/iw -> GEMM1 (GLU; epilogue converts ow in distributed
// chunks) -> GEMM2. All graph-capturable, no allocations.
// ---------------------------------------------------------------------------
extern "C" void kernel_launch(void* const* d_in, const int* in_sizes, int n_in,
                              void* d_out, int out_size)
{
    const float* x  = (const float*)d_in[0];
    const float* gw = (const float*)d_in[1];
    const float* iw = (const float*)d_in[2];
    const float* ow = (const float*)d_in[3];
    float* out = (float*)d_out;

    __half *xh, *gwh, *iwh;
    cudaGetSymbolAddress((void**)&xh,  g_xh);
    cudaGetSymbolAddress((void**)&gwh, g_gwh);
    cudaGetSymbolAddress((void**)&iwh, g_iwh);

    cvt_f2h<<<2048, 256>>>(x,  xh,  (size_t)NE * NT * ND);
    cvt_f2h<<<2048, 256>>>(gw, gwh, (size_t)NE * ND * NI);
    cvt_f2h<<<2048, 256>>>(iw, iwh, (size_t)NE * ND * NI);

    cudaFuncSetAttribute(glu_mma_kernel,
                         cudaFuncAttributeMaxDynamicSharedMemorySize, 98304);
    cudaFuncSetAttribute(out_mma_kernel,
                         cudaFuncAttributeMaxDynamicSharedMemorySize, 98304);

    // grid.x = m-tiles (fastest) so concurrent CTAs share B slabs in L2
    glu_mma_kernel<<<dim3(NT / 128, NI / 64, NE), 256, 98304>>>(ow);
    out_mma_kernel<<<dim3(NT / 128, ND / 128, NE), 256, 98304>>>(out);
}

// round 16
// speedup vs baseline: 1.0456x; 1.0007x over previous
#include <cuda_runtime.h>
#include <cuda_fp16.h>
#include <cstdint>

// Problem dims (fixed by the reference)
#define NE 8
#define NT 1024
#define ND 2048
#define NI 4096

// ---------------------------------------------------------------------------
// __device__ scratch (alloc-free rule): fp16 copies of inputs + intermediate H
// g_owh is filled by GEMM1's distributed EPILOGUE chunks (non-redundant).
// ---------------------------------------------------------------------------
__device__ __half g_xh [(size_t)NE * NT * ND];   //  32 MB
__device__ __half g_gwh[(size_t)NE * ND * NI];   // 134 MB
__device__ __half g_iwh[(size_t)NE * ND * NI];   // 134 MB
__device__ __half g_owh[(size_t)NE * NI * ND];   // 134 MB
__device__ __half g_H  [(size_t)NE * NT * NI];   //  67 MB

// ---------------------------------------------------------------------------
// PTX helpers (baseline sm_80+ instructions only — compute_103-safe)
// ---------------------------------------------------------------------------
__device__ __forceinline__ uint32_t smem_u32(const void* p) {
    uint32_t a;
    asm("{ .reg .u64 t; cvta.to.shared.u64 t, %1; cvt.u32.u64 %0, t; }"
        : "=r"(a) : "l"(p));
    return a;
}
__device__ __forceinline__ void cp16(uint32_t saddr, const void* g) {
    asm volatile("cp.async.cg.shared.global [%0], [%1], 16;"
                 :: "r"(saddr), "l"(g) : "memory");
}
__device__ __forceinline__ void cp_commit() {
    asm volatile("cp.async.commit_group;" ::: "memory");
}
template <int N> __device__ __forceinline__ void cp_wait() {
    asm volatile("cp.async.wait_group %0;" :: "n"(N) : "memory");
}
__device__ __forceinline__ void ldsm4(uint32_t* r, uint32_t a) {
    asm volatile("ldmatrix.sync.aligned.m8n8.x4.shared.b16 {%0,%1,%2,%3}, [%4];"
                 : "=r"(r[0]), "=r"(r[1]), "=r"(r[2]), "=r"(r[3]) : "r"(a));
}
__device__ __forceinline__ void ldsm4t(uint32_t* r, uint32_t a) {
    asm volatile("ldmatrix.sync.aligned.m8n8.x4.trans.shared.b16 {%0,%1,%2,%3}, [%4];"
                 : "=r"(r[0]), "=r"(r[1]), "=r"(r[2]), "=r"(r[3]) : "r"(a));
}
__device__ __forceinline__ void mma16816(float* c, const uint32_t* a,
                                         uint32_t b0, uint32_t b1) {
    asm volatile(
        "mma.sync.aligned.m16n8k16.row.col.f32.f16.f16.f32 "
        "{%0,%1,%2,%3}, {%4,%5,%6,%7}, {%8,%9}, {%0,%1,%2,%3};"
        : "+f"(c[0]), "+f"(c[1]), "+f"(c[2]), "+f"(c[3])
        : "r"(a[0]), "r"(a[1]), "r"(a[2]), "r"(a[3]), "r"(b0), "r"(b1));
}
__device__ __forceinline__ uint32_t h2u(float lo, float hi) {
    __half2 h = __floats2half2_rn(lo, hi);
    return *(uint32_t*)&h;
}
#define SWZ(b) ((b) ^ (((b) >> 3) & 0x70))   // SW128: conflict-free ldmatrix

// ---------------------------------------------------------------------------
// Kernel 0: fused fp32 -> fp16 conversion for x, gw, iw in ONE launch
// (grid-stride; streaming ld/st to spare L2). Each range is a multiple of
// 8 floats per thread-step; sizes divide evenly.
// ---------------------------------------------------------------------------
__device__ __forceinline__ void cvt_range(const float* __restrict__ s,
                                          __half* __restrict__ d, size_t n)
{
    size_t i = ((size_t)blockIdx.x * blockDim.x + threadIdx.x) * 8;
    size_t stride = (size_t)gridDim.x * blockDim.x * 8;
    for (; i < n; i += stride) {
        float4 v0 = __ldcs((const float4*)(s + i));
        float4 v1 = __ldcs((const float4*)(s + i + 4));
        uint4 o;
        o.x = h2u(v0.x, v0.y); o.y = h2u(v0.z, v0.w);
        o.z = h2u(v1.x, v1.y); o.w = h2u(v1.z, v1.w);
        __stcs((uint4*)(d + i), o);
    }
}

__global__ void cvt_all(const float* __restrict__ x,
                        const float* __restrict__ gw,
                        const float* __restrict__ iw)
{
    cvt_range(x,  g_xh,  (size_t)NE * NT * ND);
    cvt_range(gw, g_gwh, (size_t)NE * ND * NI);
    cvt_range(iw, g_iwh, (size_t)NE * ND * NI);
}

// ===========================================================================
// Kernel 1: fused dual GEMM + GLU (R10 mainloop: two barriers, loads after
//   MMA block) + distributed, NON-redundant ow conversion in the EPILOGUE
//   (overlapped by co-resident CTAs' mainloops; ow is consumed only by
//   GEMM2, which launches after this kernel).
//   BM=128, BN=64, BK=64, 3-stage cp.async, 8 warps; smem 96KB; 2 CTAs/SM.
// ===========================================================================
__global__ __launch_bounds__(256, 2)
void glu_mma_kernel(const float* __restrict__ ow)
{
    extern __shared__ char smem[];
    const uint32_t sb = smem_u32(smem);
    const int tid = threadIdx.x, warp = tid >> 5, lane = tid & 31;
    const int wm = warp & 3, wn = warp >> 2;
    const int m0 = blockIdx.x * 128, n0 = blockIdx.y * 64, e = blockIdx.z;

    const __half* Ab = g_xh  + ((size_t)e * NT + m0) * ND;
    const __half* Gb = g_gwh + ((size_t)e * ND) * NI + n0;
    const __half* Ub = g_iwh + ((size_t)e * ND) * NI + n0;

    // per-thread ldmatrix byte offsets (pre-swizzle)
    int aoff[2], boff[2];
    #pragma unroll
    for (int i = 0; i < 2; i++)
        aoff[i] = (wm * 32 + i * 16 + (lane & 15)) * 128 + (lane >> 4) * 16;
    #pragma unroll
    for (int j = 0; j < 2; j++)
        boff[j] = (lane & 15) * 128 + (wn * 32 + j * 16 + (lane >> 4) * 8) * 2;

    float accG[2][4][4] = {}, accU[2][4][4] = {};

    auto load_stage = [&](int kt, int s) {
        const uint32_t sbase = sb + s * 32768;
        const int k0 = kt * 64;
        #pragma unroll
        for (int i = 0; i < 4; i++) {            // A: 128x64 halves
            int f = tid + i * 256, r = f >> 3, c = (f & 7) * 8;
            cp16(sbase + SWZ(r * 128 + c * 2), Ab + (size_t)r * ND + k0 + c);
        }
        #pragma unroll
        for (int i = 0; i < 2; i++) {            // Bg/Bu: 64x64 halves each
            int f = tid + i * 256, r = f >> 3, c = (f & 7) * 8;
            size_t go = (size_t)(k0 + r) * NI + c;
            cp16(sbase + 16384 + SWZ(r * 128 + c * 2), Gb + go);
            cp16(sbase + 24576 + SWZ(r * 128 + c * 2), Ub + go);
        }
    };

    constexpr int KT = ND / 64;   // 32
    load_stage(0, 0); cp_commit();
    load_stage(1, 1); cp_commit();

    for (int kt = 0; kt < KT; ++kt) {
        cp_wait<1>();
        __syncthreads();
        const int s = kt % 3;
        const uint32_t sA = sb + s * 32768, sBg = sA + 16384, sBu = sA + 24576;
        #pragma unroll
        for (int kk = 0; kk < 4; ++kk) {
            uint32_t a[2][4], bg[2][4], bu[2][4];
            #pragma unroll
            for (int i = 0; i < 2; i++) ldsm4(a[i], sA + SWZ(aoff[i] + kk * 32));
            #pragma unroll
            for (int j = 0; j < 2; j++) {
                ldsm4t(bg[j], sBg + SWZ(boff[j] + kk * 2048));
                ldsm4t(bu[j], sBu + SWZ(boff[j] + kk * 2048));
            }
            #pragma unroll
            for (int i = 0; i < 2; i++)
                #pragma unroll
                for (int j = 0; j < 4; j++) {
                    mma16816(accG[i][j], a[i], bg[j >> 1][(j & 1) * 2],
                             bg[j >> 1][(j & 1) * 2 + 1]);
                    mma16816(accU[i][j], a[i], bu[j >> 1][(j & 1) * 2],
                             bu[j >> 1][(j & 1) * 2 + 1]);
                }
        }
        __syncthreads();
        if (kt + 2 < KT) load_stage(kt + 2, (kt + 2) % 3);
        cp_commit();
    }

    // Epilogue part 1: H = silu(G)*U, fp16 store.
    __half* Hd = g_H + (size_t)e * NT * NI;
    const int rb = m0 + wm * 32 + (lane >> 2);
    const int cb = n0 + wn * 32 + (lane & 3) * 2;
    #pragma unroll
    for (int i = 0; i < 2; i++)
        #pragma unroll
        for (int j = 0; j < 4; j++)
            #pragma unroll
            for (int h = 0; h < 2; h++) {   // h=0: row, h=1: row+8
                float g0 = accG[i][j][h * 2],     u0 = accU[i][j][h * 2];
                float g1 = accG[i][j][h * 2 + 1], u1 = accU[i][j][h * 2 + 1];
                float h0 = (g0 / (1.0f + __expf(-g0))) * u0;
                float h1 = (g1 / (1.0f + __expf(-g1))) * u1;
                size_t off = (size_t)(rb + i * 16 + h * 8) * NI + cb + j * 8;
                *(__half2*)(Hd + off) = __floats2half2_rn(h0, h1);
            }

    // Epilogue part 2: distributed ow convert — distinct 16384-element chunk
    // per CTA (64KB read / 32KB write), after all tensor work.
    {
        const size_t bid = (size_t)blockIdx.x +
                           (size_t)gridDim.x * (blockIdx.y +
                           (size_t)gridDim.y * blockIdx.z);     // 0..4095
        const float* src = ow + bid * 16384;
        __half* dst = g_owh + bid * 16384;
        #pragma unroll
        for (int i = 0; i < 16; i++) {
            int f = (tid + i * 256) * 4;
            float4 v = __ldcs((const float4*)(src + f));
            __stcs((uint2*)(dst + f), make_uint2(h2u(v.x, v.y), h2u(v.z, v.w)));
        }
    }
}

// ===========================================================================
// Kernel 2: out = H @ op.  (R10 structure.)  BM=128, BN=128, BK=64, 3 stages,
//   8 warps (4x2).  smem = 96KB; 2 CTAs/SM via __launch_bounds__(256,2).
//   Streaming stores for out (never re-read; protect L2 for H/ow operands).
// ===========================================================================
__global__ __launch_bounds__(256, 2)
void out_mma_kernel(float* __restrict__ out)
{
    extern __shared__ char smem[];
    const uint32_t sb = smem_u32(smem);
    const int tid = threadIdx.x, warp = tid >> 5, lane = tid & 31;
    const int wm = warp & 3, wn = warp >> 2;
    const int m0 = blockIdx.x * 128, n0 = blockIdx.y * 128, e = blockIdx.z;

    const __half* Ab = g_H   + ((size_t)e * NT + m0) * NI;
    const __half* Bb = g_owh + ((size_t)e * NI) * ND + n0;

    int aoff[2];
    #pragma unroll
    for (int i = 0; i < 2; i++)
        aoff[i] = (wm * 32 + i * 16 + (lane & 15)) * 128 + (lane >> 4) * 16;
    // B: [64 k][128 n] stored as two [64][64] halves (128B rows each)
    int bhalf[4], boff[4];
    #pragma unroll
    for (int j = 0; j < 4; j++) {
        int c = wn * 64 + j * 16 + (lane >> 4) * 8;
        bhalf[j] = (c >> 6) * 8192;
        boff[j]  = (lane & 15) * 128 + (c & 63) * 2;
    }

    float acc[2][8][4] = {};

    auto load_stage = [&](int kt, int s) {
        const uint32_t sbase = sb + s * 32768;
        const int k0 = kt * 64;
        #pragma unroll
        for (int i = 0; i < 4; i++) {            // A: 128x64
            int f = tid + i * 256, r = f >> 3, c = (f & 7) * 8;
            cp16(sbase + SWZ(r * 128 + c * 2), Ab + (size_t)r * NI + k0 + c);
        }
        #pragma unroll
        for (int i = 0; i < 4; i++) {            // B: 64x128
            int f = tid + i * 256, r = f >> 4, c = (f & 15) * 8;
            cp16(sbase + 16384 + (c >> 6) * 8192 + SWZ(r * 128 + (c & 63) * 2),
                 Bb + (size_t)(k0 + r) * ND + c);
        }
    };

    constexpr int KT = NI / 64;   // 64
    load_stage(0, 0); cp_commit();
    load_stage(1, 1); cp_commit();

    for (int kt = 0; kt < KT; ++kt) {
        cp_wait<1>();
        __syncthreads();
        const int s = kt % 3;
        const uint32_t sA = sb + s * 32768, sB = sA + 16384;
        #pragma unroll
        for (int kk = 0; kk < 4; ++kk) {
            uint32_t a[2][4], b[4][4];
            #pragma unroll
            for (int i = 0; i < 2; i++) ldsm4(a[i], sA + SWZ(aoff[i] + kk * 32));
            #pragma unroll
            for (int j = 0; j < 4; j++)
                ldsm4t(b[j], sB + bhalf[j] + SWZ(boff[j] + kk * 2048));
            #pragma unroll
            for (int i = 0; i < 2; i++)
                #pragma unroll
                for (int j = 0; j < 8; j++)
                    mma16816(acc[i][j], a[i], b[j >> 1][(j & 1) * 2],
                             b[j >> 1][(j & 1) * 2 + 1]);
        }
        __syncthreads();
        if (kt + 2 < KT) load_stage(kt + 2, (kt + 2) % 3);
        cp_commit();
    }

    // Epilogue: fp32 streaming stores (out is write-once, never re-read)
    float* Od = out + (size_t)e * NT * ND;
    const int rb = m0 + wm * 32 + (lane >> 2);
    const int cb = n0 + wn * 64 + (lane & 3) * 2;
    #pragma unroll
    for (int i = 0; i < 2; i++)
        #pragma unroll
        for (int j = 0; j < 8; j++)
            #pragma unroll
            for (int h = 0; h < 2; h++) {
                size_t off = (size_t)(rb + i * 16 + h * 8) * ND + cb + j * 8;
                float2 v = make_float2(acc[i][j][h * 2], acc[i][j][h * 2 + 1]);
                __stcs((float2*)(Od + off), v);
            }
}

// ---------------------------------------------------------------------------
// Harness entry. Inputs: x, gate_proj, inner_proj, output_proj (all fp32).
// Sequence: cvt_all (x+gw+iw, one launch) -> GEMM1 (GLU; epilogue converts
// ow in distributed chunks) -> GEMM2. All graph-capturable, no allocations.
// ---------------------------------------------------------------------------
extern "C" void kernel_launch(void* const* d_in, const int* in_sizes, int n_in,
                              void* d_out, int out_size)
{
    const float* x  = (const float*)d_in[0];
    const float* gw = (const float*)d_in[1];
    const float* iw = (const float*)d_in[2];
    const float* ow = (const float*)d_in[3];
    float* out = (float*)d_out;

    cvt_all<<<2048, 256>>>(x, gw, iw);

    cudaFuncSetAttribute(glu_mma_kernel,
                         cudaFuncAttributeMaxDynamicSharedMemorySize, 98304);
    cudaFuncSetAttribute(out_mma_kernel,
                         cudaFuncAttributeMaxDynamicSharedMemorySize, 98304);

    // grid.x = m-tiles (fastest) so concurrent CTAs share B slabs in L2
    glu_mma_kernel<<<dim3(NT / 128, NI / 64, NE), 256, 98304>>>(ow);
    out_mma_kernel<<<dim3(NT / 128, ND / 128, NE), 256, 98304>>>(out);
}

// round 17
// speedup vs baseline: 1.0547x; 1.0087x over previous
#include <cuda_runtime.h>
#include <cuda_fp16.h>
#include <cstdint>

// Problem dims (fixed by the reference)
#define NE 8
#define NT 1024
#define ND 2048
#define NI 4096

// ---------------------------------------------------------------------------
// __device__ scratch (alloc-free rule): fp16 copies of inputs + intermediate H
// g_owh is filled by GEMM1's distributed EPILOGUE chunks (non-redundant).
// ---------------------------------------------------------------------------
__device__ __half g_xh [(size_t)NE * NT * ND];   //  32 MB
__device__ __half g_gwh[(size_t)NE * ND * NI];   // 134 MB
__device__ __half g_iwh[(size_t)NE * ND * NI];   // 134 MB
__device__ __half g_owh[(size_t)NE * NI * ND];   // 134 MB
__device__ __half g_H  [(size_t)NE * NT * NI];   //  67 MB

// ---------------------------------------------------------------------------
// PTX helpers (baseline sm_80+ instructions only — compute_103-safe)
// ---------------------------------------------------------------------------
__device__ __forceinline__ uint32_t smem_u32(const void* p) {
    uint32_t a;
    asm("{ .reg .u64 t; cvta.to.shared.u64 t, %1; cvt.u32.u64 %0, t; }"
        : "=r"(a) : "l"(p));
    return a;
}
__device__ __forceinline__ void cp16(uint32_t saddr, const void* g) {
    asm volatile("cp.async.cg.shared.global [%0], [%1], 16;"
                 :: "r"(saddr), "l"(g) : "memory");
}
__device__ __forceinline__ void cp_commit() {
    asm volatile("cp.async.commit_group;" ::: "memory");
}
template <int N> __device__ __forceinline__ void cp_wait() {
    asm volatile("cp.async.wait_group %0;" :: "n"(N) : "memory");
}
__device__ __forceinline__ void ldsm4(uint32_t* r, uint32_t a) {
    asm volatile("ldmatrix.sync.aligned.m8n8.x4.shared.b16 {%0,%1,%2,%3}, [%4];"
                 : "=r"(r[0]), "=r"(r[1]), "=r"(r[2]), "=r"(r[3]) : "r"(a));
}
__device__ __forceinline__ void ldsm4t(uint32_t* r, uint32_t a) {
    asm volatile("ldmatrix.sync.aligned.m8n8.x4.trans.shared.b16 {%0,%1,%2,%3}, [%4];"
                 : "=r"(r[0]), "=r"(r[1]), "=r"(r[2]), "=r"(r[3]) : "r"(a));
}
__device__ __forceinline__ void mma16816(float* c, const uint32_t* a,
                                         uint32_t b0, uint32_t b1) {
    asm volatile(
        "mma.sync.aligned.m16n8k16.row.col.f32.f16.f16.f32 "
        "{%0,%1,%2,%3}, {%4,%5,%6,%7}, {%8,%9}, {%0,%1,%2,%3};"
        : "+f"(c[0]), "+f"(c[1]), "+f"(c[2]), "+f"(c[3])
        : "r"(a[0]), "r"(a[1]), "r"(a[2]), "r"(a[3]), "r"(b0), "r"(b1));
}
__device__ __forceinline__ uint32_t h2u(float lo, float hi) {
    __half2 h = __floats2half2_rn(lo, hi);
    return *(uint32_t*)&h;
}
#define SWZ(b) ((b) ^ (((b) >> 3) & 0x70))   // SW128: conflict-free ldmatrix

// ---------------------------------------------------------------------------
// Kernel 0: fused fp32 -> fp16 conversion for x, gw, iw in ONE launch.
// 16 floats (4 x LDG.128) per thread-iteration for higher MLP; streaming
// ld/st to spare L2. All sizes are multiples of 16 floats per thread-step.
// ---------------------------------------------------------------------------
__device__ __forceinline__ void cvt_range(const float* __restrict__ s,
                                          __half* __restrict__ d, size_t n)
{
    size_t i = ((size_t)blockIdx.x * blockDim.x + threadIdx.x) * 16;
    size_t stride = (size_t)gridDim.x * blockDim.x * 16;
    for (; i < n; i += stride) {
        float4 v0 = __ldcs((const float4*)(s + i));
        float4 v1 = __ldcs((const float4*)(s + i + 4));
        float4 v2 = __ldcs((const float4*)(s + i + 8));
        float4 v3 = __ldcs((const float4*)(s + i + 12));
        uint4 o0, o1;
        o0.x = h2u(v0.x, v0.y); o0.y = h2u(v0.z, v0.w);
        o0.z = h2u(v1.x, v1.y); o0.w = h2u(v1.z, v1.w);
        o1.x = h2u(v2.x, v2.y); o1.y = h2u(v2.z, v2.w);
        o1.z = h2u(v3.x, v3.y); o1.w = h2u(v3.z, v3.w);
        __stcs((uint4*)(d + i), o0);
        __stcs((uint4*)(d + i + 8), o1);
    }
}

__global__ void cvt_all(const float* __restrict__ x,
                        const float* __restrict__ gw,
                        const float* __restrict__ iw)
{
    cvt_range(x,  g_xh,  (size_t)NE * NT * ND);
    cvt_range(gw, g_gwh, (size_t)NE * ND * NI);
    cvt_range(iw, g_iwh, (size_t)NE * ND * NI);
}

// ===========================================================================
// Kernel 1: fused dual GEMM + GLU (R10 mainloop: two barriers, loads after
//   MMA block) + distributed, NON-redundant ow conversion in the EPILOGUE
//   (overlapped by co-resident CTAs' mainloops; ow is consumed only by
//   GEMM2, which launches after this kernel).
//   BM=128, BN=64, BK=64, 3-stage cp.async, 8 warps; smem 96KB; 2 CTAs/SM.
// ===========================================================================
__global__ __launch_bounds__(256, 2)
void glu_mma_kernel(const float* __restrict__ ow)
{
    extern __shared__ char smem[];
    const uint32_t sb = smem_u32(smem);
    const int tid = threadIdx.x, warp = tid >> 5, lane = tid & 31;
    const int wm = warp & 3, wn = warp >> 2;
    const int m0 = blockIdx.x * 128, n0 = blockIdx.y * 64, e = blockIdx.z;

    const __half* Ab = g_xh  + ((size_t)e * NT + m0) * ND;
    const __half* Gb = g_gwh + ((size_t)e * ND) * NI + n0;
    const __half* Ub = g_iwh + ((size_t)e * ND) * NI + n0;

    // per-thread ldmatrix byte offsets (pre-swizzle)
    int aoff[2], boff[2];
    #pragma unroll
    for (int i = 0; i < 2; i++)
        aoff[i] = (wm * 32 + i * 16 + (lane & 15)) * 128 + (lane >> 4) * 16;
    #pragma unroll
    for (int j = 0; j < 2; j++)
        boff[j] = (lane & 15) * 128 + (wn * 32 + j * 16 + (lane >> 4) * 8) * 2;

    float accG[2][4][4] = {}, accU[2][4][4] = {};

    auto load_stage = [&](int kt, int s) {
        const uint32_t sbase = sb + s * 32768;
        const int k0 = kt * 64;
        #pragma unroll
        for (int i = 0; i < 4; i++) {            // A: 128x64 halves
            int f = tid + i * 256, r = f >> 3, c = (f & 7) * 8;
            cp16(sbase + SWZ(r * 128 + c * 2), Ab + (size_t)r * ND + k0 + c);
        }
        #pragma unroll
        for (int i = 0; i < 2; i++) {            // Bg/Bu: 64x64 halves each
            int f = tid + i * 256, r = f >> 3, c = (f & 7) * 8;
            size_t go = (size_t)(k0 + r) * NI + c;
            cp16(sbase + 16384 + SWZ(r * 128 + c * 2), Gb + go);
            cp16(sbase + 24576 + SWZ(r * 128 + c * 2), Ub + go);
        }
    };

    constexpr int KT = ND / 64;   // 32
    load_stage(0, 0); cp_commit();
    load_stage(1, 1); cp_commit();

    for (int kt = 0; kt < KT; ++kt) {
        cp_wait<1>();
        __syncthreads();
        const int s = kt % 3;
        const uint32_t sA = sb + s * 32768, sBg = sA + 16384, sBu = sA + 24576;
        #pragma unroll
        for (int kk = 0; kk < 4; ++kk) {
            uint32_t a[2][4], bg[2][4], bu[2][4];
            #pragma unroll
            for (int i = 0; i < 2; i++) ldsm4(a[i], sA + SWZ(aoff[i] + kk * 32));
            #pragma unroll
            for (int j = 0; j < 2; j++) {
                ldsm4t(bg[j], sBg + SWZ(boff[j] + kk * 2048));
                ldsm4t(bu[j], sBu + SWZ(boff[j] + kk * 2048));
            }
            #pragma unroll
            for (int i = 0; i < 2; i++)
                #pragma unroll
                for (int j = 0; j < 4; j++) {
                    mma16816(accG[i][j], a[i], bg[j >> 1][(j & 1) * 2],
                             bg[j >> 1][(j & 1) * 2 + 1]);
                    mma16816(accU[i][j], a[i], bu[j >> 1][(j & 1) * 2],
                             bu[j >> 1][(j & 1) * 2 + 1]);
                }
        }
        __syncthreads();
        if (kt + 2 < KT) load_stage(kt + 2, (kt + 2) % 3);
        cp_commit();
    }

    // Epilogue part 1: H = silu(G)*U, fp16 store.
    __half* Hd = g_H + (size_t)e * NT * NI;
    const int rb = m0 + wm * 32 + (lane >> 2);
    const int cb = n0 + wn * 32 + (lane & 3) * 2;
    #pragma unroll
    for (int i = 0; i < 2; i++)
        #pragma unroll
        for (int j = 0; j < 4; j++)
            #pragma unroll
            for (int h = 0; h < 2; h++) {   // h=0: row, h=1: row+8
                float g0 = accG[i][j][h * 2],     u0 = accU[i][j][h * 2];
                float g1 = accG[i][j][h * 2 + 1], u1 = accU[i][j][h * 2 + 1];
                float h0 = (g0 / (1.0f + __expf(-g0))) * u0;
                float h1 = (g1 / (1.0f + __expf(-g1))) * u1;
                size_t off = (size_t)(rb + i * 16 + h * 8) * NI + cb + j * 8;
                *(__half2*)(Hd + off) = __floats2half2_rn(h0, h1);
            }

    // Epilogue part 2: distributed ow convert — distinct 16384-element chunk
    // per CTA (64KB read / 32KB write), after all tensor work.
    {
        const size_t bid = (size_t)blockIdx.x +
                           (size_t)gridDim.x * (blockIdx.y +
                           (size_t)gridDim.y * blockIdx.z);     // 0..4095
        const float* src = ow + bid * 16384;
        __half* dst = g_owh + bid * 16384;
        #pragma unroll
        for (int i = 0; i < 16; i++) {
            int f = (tid + i * 256) * 4;
            float4 v = __ldcs((const float4*)(src + f));
            __stcs((uint2*)(dst + f), make_uint2(h2u(v.x, v.y), h2u(v.z, v.w)));
        }
    }
}

// ===========================================================================
// Kernel 2: out = H @ op.  (R10 structure.)  BM=128, BN=128, BK=64, 3 stages,
//   8 warps (4x2).  smem = 96KB; 2 CTAs/SM via __launch_bounds__(256,2).
//   Streaming stores for out (never re-read; protect L2 for H/ow operands).
// ===========================================================================
__global__ __launch_bounds__(256, 2)
void out_mma_kernel(float* __restrict__ out)
{
    extern __shared__ char smem[];
    const uint32_t sb = smem_u32(smem);
    const int tid = threadIdx.x, warp = tid >> 5, lane = tid & 31;
    const int wm = warp & 3, wn = warp >> 2;
    const int m0 = blockIdx.x * 128, n0 = blockIdx.y * 128, e = blockIdx.z;

    const __half* Ab = g_H   + ((size_t)e * NT + m0) * NI;
    const __half* Bb = g_owh + ((size_t)e * NI) * ND + n0;

    int aoff[2];
    #pragma unroll
    for (int i = 0; i < 2; i++)
        aoff[i] = (wm * 32 + i * 16 + (lane & 15)) * 128 + (lane >> 4) * 16;
    // B: [64 k][128 n] stored as two [64][64] halves (128B rows each)
    int bhalf[4], boff[4];
    #pragma unroll
    for (int j = 0; j < 4; j++) {
        int c = wn * 64 + j * 16 + (lane >> 4) * 8;
        bhalf[j] = (c >> 6) * 8192;
        boff[j]  = (lane & 15) * 128 + (c & 63) * 2;
    }

    float acc[2][8][4] = {};

    auto load_stage = [&](int kt, int s) {
        const uint32_t sbase = sb + s * 32768;
        const int k0 = kt * 64;
        #pragma unroll
        for (int i = 0; i < 4; i++) {            // A: 128x64
            int f = tid + i * 256, r = f >> 3, c = (f & 7) * 8;
            cp16(sbase + SWZ(r * 128 + c * 2), Ab + (size_t)r * NI + k0 + c);
        }
        #pragma unroll
        for (int i = 0; i < 4; i++) {            // B: 64x128
            int f = tid + i * 256, r = f >> 4, c = (f & 15) * 8;
            cp16(sbase + 16384 + (c >> 6) * 8192 + SWZ(r * 128 + (c & 63) * 2),
                 Bb + (size_t)(k0 + r) * ND + c);
        }
    };

    constexpr int KT = NI / 64;   // 64
    load_stage(0, 0); cp_commit();
    load_stage(1, 1); cp_commit();

    for (int kt = 0; kt < KT; ++kt) {
        cp_wait<1>();
        __syncthreads();
        const int s = kt % 3;
        const uint32_t sA = sb + s * 32768, sB = sA + 16384;
        #pragma unroll
        for (int kk = 0; kk < 4; ++kk) {
            uint32_t a[2][4], b[4][4];
            #pragma unroll
            for (int i = 0; i < 2; i++) ldsm4(a[i], sA + SWZ(aoff[i] + kk * 32));
            #pragma unroll
            for (int j = 0; j < 4; j++)
                ldsm4t(b[j], sB + bhalf[j] + SWZ(boff[j] + kk * 2048));
            #pragma unroll
            for (int i = 0; i < 2; i++)
                #pragma unroll
                for (int j = 0; j < 8; j++)
                    mma16816(acc[i][j], a[i], b[j >> 1][(j & 1) * 2],
                             b[j >> 1][(j & 1) * 2 + 1]);
        }
        __syncthreads();
        if (kt + 2 < KT) load_stage(kt + 2, (kt + 2) % 3);
        cp_commit();
    }

    // Epilogue: fp32 streaming stores (out is write-once, never re-read)
    float* Od = out + (size_t)e * NT * ND;
    const int rb = m0 + wm * 32 + (lane >> 2);
    const int cb = n0 + wn * 64 + (lane & 3) * 2;
    #pragma unroll
    for (int i = 0; i < 2; i++)
        #pragma unroll
        for (int j = 0; j < 8; j++)
            #pragma unroll
            for (int h = 0; h < 2; h++) {
                size_t off = (size_t)(rb + i * 16 + h * 8) * ND + cb + j * 8;
                float2 v = make_float2(acc[i][j][h * 2], acc[i][j][h * 2 + 1]);
                __stcs((float2*)(Od + off), v);
            }
}

// ---------------------------------------------------------------------------
// Harness entry. Inputs: x, gate_proj, inner_proj, output_proj (all fp32).
// Sequence: cvt_all (x+gw+iw, one launch) -> GEMM1 (GLU; epilogue converts
// ow in distributed chunks) -> GEMM2. All graph-capturable, no allocations.
// ---------------------------------------------------------------------------
extern "C" void kernel_launch(void* const* d_in, const int* in_sizes, int n_in,
                              void* d_out, int out_size)
{
    const float* x  = (const float*)d_in[0];
    const float* gw = (const float*)d_in[1];
    const float* iw = (const float*)d_in[2];
    const float* ow = (const float*)d_in[3];
    float* out = (float*)d_out;

    cvt_all<<<4096, 256>>>(x, gw, iw);

    cudaFuncSetAttribute(glu_mma_kernel,
                         cudaFuncAttributeMaxDynamicSharedMemorySize, 98304);
    cudaFuncSetAttribute(out_mma_kernel,
                         cudaFuncAttributeMaxDynamicSharedMemorySize, 98304);

    // grid.x = m-tiles (fastest) so concurrent CTAs share B slabs in L2
    glu_mma_kernel<<<dim3(NT / 128, NI / 64, NE), 256, 98304>>>(ow);
    out_mma_kernel<<<dim3(NT / 128, ND / 128, NE), 256, 98304>>>(out);
}